// round 1
// baseline (speedup 1.0000x reference)
#include <cuda_runtime.h>
#include <math.h>
#include <stdint.h>

#define N_TOK 4096
#define D_DIM 2048
#define F_DIM 8192
#define E_EXP 8
#define R_RANK 8
#define SCALING 2.0f

#define BM 128
#define BN 128
#define BK 16
#define TM 8
#define TN 8

// Scratch (static __device__ arrays; no allocation at runtime)
__device__ float g_buf[(size_t)N_TOK * F_DIM];          // 128 MB: w0*h0 + w1*h1
__device__ float h_buf[2ull * N_TOK * F_DIM];           // 256 MB: h0, h1
__device__ float z1c[N_TOK * 2 * R_RANK];               // SCALING * (x . A1[e,r])
__device__ float z2s[N_TOK * 2 * R_RANK];               // SCALING * w_k * (h_k . A2[e,r])
__device__ int   eidx[N_TOK * 2];
__device__ float ew[N_TOK * 2];
__device__ float wsum_buf[N_TOK];

__device__ __forceinline__ float gelu_new(float x) {
    float x3 = x * x * x;
    float t = tanhf(0.7978845608028654f * (x + 0.044715f * x3));
    return 0.5f * x * (1.0f + t);
}

// ---------------------------------------------------------------------------
// Router: logits -> softmax -> top2, plus z1 coefficients (x . A1[e,r])
// One block per token, 256 threads.
// ---------------------------------------------------------------------------
__global__ __launch_bounds__(256) void router_kernel(
    const float* __restrict__ x, const float* __restrict__ Wr,
    const float* __restrict__ br, const float* __restrict__ A1)
{
    int n = blockIdx.x;
    int tid = threadIdx.x;
    __shared__ float xs[D_DIM];
    __shared__ float red[E_EXP][8];
    __shared__ float red2[16][8];
    __shared__ int s_idx[2];

    for (int d = tid; d < D_DIM; d += 256) xs[d] = x[(size_t)n * D_DIM + d];
    __syncthreads();

    // logits for all 8 experts
    float acc[E_EXP];
#pragma unroll
    for (int e = 0; e < E_EXP; e++) acc[e] = 0.f;
    for (int d = tid; d < D_DIM; d += 256) {
        float xv = xs[d];
#pragma unroll
        for (int e = 0; e < E_EXP; e++) acc[e] += xv * Wr[e * D_DIM + d];
    }
#pragma unroll
    for (int e = 0; e < E_EXP; e++) {
        float v = acc[e];
        for (int o = 16; o > 0; o >>= 1) v += __shfl_down_sync(0xffffffffu, v, o);
        if ((tid & 31) == 0) red[e][tid >> 5] = v;
    }
    __syncthreads();

    if (tid == 0) {
        float logits[E_EXP];
#pragma unroll
        for (int e = 0; e < E_EXP; e++) {
            float v = 0.f;
#pragma unroll
            for (int w = 0; w < 8; w++) v += red[e][w];
            logits[e] = v + br[e];
        }
        float mx = logits[0];
#pragma unroll
        for (int e = 1; e < E_EXP; e++) mx = fmaxf(mx, logits[e]);
        float p[E_EXP], se = 0.f;
#pragma unroll
        for (int e = 0; e < E_EXP; e++) { p[e] = expf(logits[e] - mx); se += p[e]; }
        float inv = 1.0f / se;
#pragma unroll
        for (int e = 0; e < E_EXP; e++) p[e] *= inv;
        // top-2, lowest index wins ties (matches jax top_k)
        int i0 = 0;
#pragma unroll
        for (int e = 1; e < E_EXP; e++) if (p[e] > p[i0]) i0 = e;
        int i1 = -1;
#pragma unroll
        for (int e = 0; e < E_EXP; e++) {
            if (e == i0) continue;
            if (i1 < 0 || p[e] > p[i1]) i1 = e;
        }
        s_idx[0] = i0; s_idx[1] = i1;
        eidx[2 * n] = i0; eidx[2 * n + 1] = i1;
        ew[2 * n] = p[i0]; ew[2 * n + 1] = p[i1];
        wsum_buf[n] = p[i0] + p[i1];
    }
    __syncthreads();

    // z1 coefficients for the 2 selected experts: 16 dots over D
    int e0 = s_idx[0], e1 = s_idx[1];
    float uacc[16];
#pragma unroll
    for (int i = 0; i < 16; i++) uacc[i] = 0.f;
    for (int d = tid; d < D_DIM; d += 256) {
        float xv = xs[d];
#pragma unroll
        for (int r = 0; r < R_RANK; r++) {
            uacc[r]     += xv * A1[((size_t)e0 * R_RANK + r) * D_DIM + d];
            uacc[8 + r] += xv * A1[((size_t)e1 * R_RANK + r) * D_DIM + d];
        }
    }
#pragma unroll
    for (int i = 0; i < 16; i++) {
        float v = uacc[i];
        for (int o = 16; o > 0; o >>= 1) v += __shfl_down_sync(0xffffffffu, v, o);
        if ((tid & 31) == 0) red2[i][tid >> 5] = v;
    }
    __syncthreads();
    if (tid < 16) {
        float v = 0.f;
#pragma unroll
        for (int w = 0; w < 8; w++) v += red2[tid][w];
        z1c[n * 16 + tid] = v * SCALING;
    }
}

// ---------------------------------------------------------------------------
// fc1: base = x @ W1^T, epilogue adds per-expert rank-8 LoRA, gelu,
// writes h0, h1 and g = w0*h0 + w1*h1.
// ---------------------------------------------------------------------------
__global__ __launch_bounds__(256, 2) void fc1_kernel(
    const float* __restrict__ A,   // x [N, D]
    const float* __restrict__ B,   // W1 [F, D]
    const float* __restrict__ b1,
    const float* __restrict__ B1)  // [E, F, R]
{
    const int K = D_DIM;
    int bn = blockIdx.x, bm = blockIdx.y;
    int tid = threadIdx.x;
    __shared__ float As[BK][BM + 4];
    __shared__ float Bs[BK][BN + 4];
    float acc[TM][TN];
#pragma unroll
    for (int i = 0; i < TM; i++)
#pragma unroll
        for (int j = 0; j < TN; j++) acc[i][j] = 0.f;

    int tx = tid % 16, ty = tid / 16;
    const float* Ab = A + (size_t)bm * BM * K;
    const float* Bb = B + (size_t)bn * BN * K;
    int rowL = tid >> 2;
    int colL = (tid & 3) * 4;

    for (int k0 = 0; k0 < K; k0 += BK) {
#pragma unroll
        for (int i = 0; i < 2; i++) {
            float4 a = *(const float4*)(Ab + (size_t)(rowL + i * 64) * K + k0 + colL);
            As[colL + 0][rowL + i * 64] = a.x;
            As[colL + 1][rowL + i * 64] = a.y;
            As[colL + 2][rowL + i * 64] = a.z;
            As[colL + 3][rowL + i * 64] = a.w;
            float4 b = *(const float4*)(Bb + (size_t)(rowL + i * 64) * K + k0 + colL);
            Bs[colL + 0][rowL + i * 64] = b.x;
            Bs[colL + 1][rowL + i * 64] = b.y;
            Bs[colL + 2][rowL + i * 64] = b.z;
            Bs[colL + 3][rowL + i * 64] = b.w;
        }
        __syncthreads();
#pragma unroll
        for (int kk = 0; kk < BK; kk++) {
            float4 a0 = *(const float4*)&As[kk][ty * TM];
            float4 a1 = *(const float4*)&As[kk][ty * TM + 4];
            float4 b0 = *(const float4*)&Bs[kk][tx * TN];
            float4 b1v = *(const float4*)&Bs[kk][tx * TN + 4];
            float ra[8] = {a0.x, a0.y, a0.z, a0.w, a1.x, a1.y, a1.z, a1.w};
            float rb[8] = {b0.x, b0.y, b0.z, b0.w, b1v.x, b1v.y, b1v.z, b1v.w};
#pragma unroll
            for (int i = 0; i < TM; i++)
#pragma unroll
                for (int j = 0; j < TN; j++) acc[i][j] += ra[i] * rb[j];
        }
        __syncthreads();
    }

    int nrow0 = bm * BM + ty * TM;
    int fcol0 = bn * BN + tx * TN;
#pragma unroll
    for (int i = 0; i < TM; i++) {
        int n = nrow0 + i;
        int e0 = eidx[2 * n], e1 = eidx[2 * n + 1];
        float w0 = ew[2 * n], w1 = ew[2 * n + 1];
        const float4* zp = (const float4*)&z1c[n * 16];
        float4 z0a = zp[0], z0b = zp[1], z1a = zp[2], z1b = zp[3];
        float h0v[TN], h1v[TN], gv[TN];
#pragma unroll
        for (int j = 0; j < TN; j++) {
            int f = fcol0 + j;
            float c = acc[i][j] + b1[f];
            const float4* q0 = (const float4*)&B1[((size_t)e0 * F_DIM + f) * R_RANK];
            float4 u0 = q0[0], u1 = q0[1];
            float l0 = z0a.x * u0.x + z0a.y * u0.y + z0a.z * u0.z + z0a.w * u0.w
                     + z0b.x * u1.x + z0b.y * u1.y + z0b.z * u1.z + z0b.w * u1.w;
            const float4* q1 = (const float4*)&B1[((size_t)e1 * F_DIM + f) * R_RANK];
            float4 v0 = q1[0], v1 = q1[1];
            float l1 = z1a.x * v0.x + z1a.y * v0.y + z1a.z * v0.z + z1a.w * v0.w
                     + z1b.x * v1.x + z1b.y * v1.y + z1b.z * v1.z + z1b.w * v1.w;
            float h0 = gelu_new(c + l0);
            float h1 = gelu_new(c + l1);
            h0v[j] = h0; h1v[j] = h1;
            gv[j] = w0 * h0 + w1 * h1;
        }
        size_t off = (size_t)n * F_DIM + fcol0;
        *(float4*)&h_buf[off]     = make_float4(h0v[0], h0v[1], h0v[2], h0v[3]);
        *(float4*)&h_buf[off + 4] = make_float4(h0v[4], h0v[5], h0v[6], h0v[7]);
        size_t off1 = off + (size_t)N_TOK * F_DIM;
        *(float4*)&h_buf[off1]     = make_float4(h1v[0], h1v[1], h1v[2], h1v[3]);
        *(float4*)&h_buf[off1 + 4] = make_float4(h1v[4], h1v[5], h1v[6], h1v[7]);
        *(float4*)&g_buf[off]     = make_float4(gv[0], gv[1], gv[2], gv[3]);
        *(float4*)&g_buf[off + 4] = make_float4(gv[4], gv[5], gv[6], gv[7]);
    }
}

// ---------------------------------------------------------------------------
// z2: z2s[n,k,r] = SCALING * w_k * sum_f h_k[n,f] * A2[e_k, r, f]
// One block per (token, k).
// ---------------------------------------------------------------------------
__global__ __launch_bounds__(256) void z2_kernel(const float* __restrict__ A2)
{
    int n = blockIdx.x;
    int k = blockIdx.y;
    int tid = threadIdx.x;
    int e = eidx[2 * n + k];
    const float* h = h_buf + (size_t)k * N_TOK * F_DIM + (size_t)n * F_DIM;
    const float* a2 = A2 + (size_t)e * R_RANK * F_DIM;

    float acc[R_RANK];
#pragma unroll
    for (int r = 0; r < R_RANK; r++) acc[r] = 0.f;

    for (int f = tid * 4; f < F_DIM; f += 1024) {
        float4 hv = *(const float4*)(h + f);
#pragma unroll
        for (int r = 0; r < R_RANK; r++) {
            float4 av = *(const float4*)(a2 + (size_t)r * F_DIM + f);
            acc[r] += hv.x * av.x + hv.y * av.y + hv.z * av.z + hv.w * av.w;
        }
    }

    __shared__ float red[R_RANK][8];
#pragma unroll
    for (int r = 0; r < R_RANK; r++) {
        float v = acc[r];
        for (int o = 16; o > 0; o >>= 1) v += __shfl_down_sync(0xffffffffu, v, o);
        if ((tid & 31) == 0) red[r][tid >> 5] = v;
    }
    __syncthreads();
    if (tid < R_RANK) {
        float v = 0.f;
#pragma unroll
        for (int w = 0; w < 8; w++) v += red[tid][w];
        z2s[n * 16 + k * 8 + tid] = v * SCALING * ew[2 * n + k];
    }
}

// ---------------------------------------------------------------------------
// fc2: out = g @ W2^T + (w0+w1)*b2 + sum_k z2s[n,k,:] . B2[e_k, d, :]
// ---------------------------------------------------------------------------
__global__ __launch_bounds__(256, 2) void fc2_kernel(
    const float* __restrict__ B,   // W2 [D, F]
    const float* __restrict__ b2,
    const float* __restrict__ B2,  // [E, D, R]
    float* __restrict__ out)
{
    const int K = F_DIM;
    int bn = blockIdx.x, bm = blockIdx.y;
    int tid = threadIdx.x;
    __shared__ float As[BK][BM + 4];
    __shared__ float Bs[BK][BN + 4];
    float acc[TM][TN];
#pragma unroll
    for (int i = 0; i < TM; i++)
#pragma unroll
        for (int j = 0; j < TN; j++) acc[i][j] = 0.f;

    int tx = tid % 16, ty = tid / 16;
    const float* Ab = g_buf + (size_t)bm * BM * K;
    const float* Bb = B + (size_t)bn * BN * K;
    int rowL = tid >> 2;
    int colL = (tid & 3) * 4;

    for (int k0 = 0; k0 < K; k0 += BK) {
#pragma unroll
        for (int i = 0; i < 2; i++) {
            float4 a = *(const float4*)(Ab + (size_t)(rowL + i * 64) * K + k0 + colL);
            As[colL + 0][rowL + i * 64] = a.x;
            As[colL + 1][rowL + i * 64] = a.y;
            As[colL + 2][rowL + i * 64] = a.z;
            As[colL + 3][rowL + i * 64] = a.w;
            float4 b = *(const float4*)(Bb + (size_t)(rowL + i * 64) * K + k0 + colL);
            Bs[colL + 0][rowL + i * 64] = b.x;
            Bs[colL + 1][rowL + i * 64] = b.y;
            Bs[colL + 2][rowL + i * 64] = b.z;
            Bs[colL + 3][rowL + i * 64] = b.w;
        }
        __syncthreads();
#pragma unroll
        for (int kk = 0; kk < BK; kk++) {
            float4 a0 = *(const float4*)&As[kk][ty * TM];
            float4 a1 = *(const float4*)&As[kk][ty * TM + 4];
            float4 b0 = *(const float4*)&Bs[kk][tx * TN];
            float4 b1v = *(const float4*)&Bs[kk][tx * TN + 4];
            float ra[8] = {a0.x, a0.y, a0.z, a0.w, a1.x, a1.y, a1.z, a1.w};
            float rb[8] = {b0.x, b0.y, b0.z, b0.w, b1v.x, b1v.y, b1v.z, b1v.w};
#pragma unroll
            for (int i = 0; i < TM; i++)
#pragma unroll
                for (int j = 0; j < TN; j++) acc[i][j] += ra[i] * rb[j];
        }
        __syncthreads();
    }

    int nrow0 = bm * BM + ty * TM;
    int dcol0 = bn * BN + tx * TN;
#pragma unroll
    for (int i = 0; i < TM; i++) {
        int n = nrow0 + i;
        float ws = wsum_buf[n];
        int e0 = eidx[2 * n], e1 = eidx[2 * n + 1];
        const float4* zp = (const float4*)&z2s[n * 16];
        float4 z0a = zp[0], z0b = zp[1], z1a = zp[2], z1b = zp[3];
        float ov[TN];
#pragma unroll
        for (int j = 0; j < TN; j++) {
            int d = dcol0 + j;
            float c = acc[i][j] + ws * b2[d];
            const float4* q0 = (const float4*)&B2[((size_t)e0 * D_DIM + d) * R_RANK];
            float4 u0 = q0[0], u1 = q0[1];
            c += z0a.x * u0.x + z0a.y * u0.y + z0a.z * u0.z + z0a.w * u0.w
               + z0b.x * u1.x + z0b.y * u1.y + z0b.z * u1.z + z0b.w * u1.w;
            const float4* q1 = (const float4*)&B2[((size_t)e1 * D_DIM + d) * R_RANK];
            float4 v0 = q1[0], v1 = q1[1];
            c += z1a.x * v0.x + z1a.y * v0.y + z1a.z * v0.z + z1a.w * v0.w
               + z1b.x * v1.x + z1b.y * v1.y + z1b.z * v1.z + z1b.w * v1.w;
            ov[j] = c;
        }
        size_t off = (size_t)n * D_DIM + dcol0;
        *(float4*)&out[off]     = make_float4(ov[0], ov[1], ov[2], ov[3]);
        *(float4*)&out[off + 4] = make_float4(ov[4], ov[5], ov[6], ov[7]);
    }
}

extern "C" void kernel_launch(void* const* d_in, const int* in_sizes, int n_in,
                              void* d_out, int out_size)
{
    const float* x  = (const float*)d_in[0];
    const float* Wr = (const float*)d_in[1];
    const float* br = (const float*)d_in[2];
    const float* W1 = (const float*)d_in[3];
    const float* b1 = (const float*)d_in[4];
    const float* W2 = (const float*)d_in[5];
    const float* b2 = (const float*)d_in[6];
    const float* A1 = (const float*)d_in[7];
    const float* B1 = (const float*)d_in[8];
    const float* A2 = (const float*)d_in[9];
    const float* B2 = (const float*)d_in[10];
    float* out = (float*)d_out;

    router_kernel<<<N_TOK, 256>>>(x, Wr, br, A1);
    fc1_kernel<<<dim3(F_DIM / BN, N_TOK / BM), 256>>>(x, W1, b1, B1);
    z2_kernel<<<dim3(N_TOK, 2), 256>>>(A2);
    fc2_kernel<<<dim3(D_DIM / BN, N_TOK / BM), 256>>>(W2, b2, B2, out);
}

// round 2
// speedup vs baseline: 1.0008x; 1.0008x over previous
#include <cuda_runtime.h>
#include <math.h>
#include <stdint.h>

#define N_TOK 4096
#define D_DIM 2048
#define F_DIM 8192
#define E_EXP 8
#define R_RANK 8
#define SCALING 2.0f

#define BM 128
#define BN 128
#define BK 16
#define TM 8
#define TN 8

// Scratch (static __device__ arrays; no allocation at runtime)
__device__ float g_buf[(size_t)N_TOK * F_DIM];          // 128 MB: w0*h0 + w1*h1
__device__ float h_buf[2ull * N_TOK * F_DIM];           // 256 MB: h0, h1
__device__ float z1c[N_TOK * 2 * R_RANK];               // SCALING * (x . A1[e,r])
__device__ float z2s[N_TOK * 2 * R_RANK];               // SCALING * w_k * (h_k . A2[e,r])
__device__ int   eidx[N_TOK * 2];
__device__ float ew[N_TOK * 2];
__device__ float wsum_buf[N_TOK];

__device__ __forceinline__ float gelu_new(float x) {
    float x3 = x * x * x;
    float t = tanhf(0.7978845608028654f * (x + 0.044715f * x3));
    return 0.5f * x * (1.0f + t);
}

// ---------------------------------------------------------------------------
// Router: logits -> softmax -> top2, plus z1 coefficients (x . A1[e,r])
// One block per token, 256 threads.
// ---------------------------------------------------------------------------
__global__ __launch_bounds__(256) void router_kernel(
    const float* __restrict__ x, const float* __restrict__ Wr,
    const float* __restrict__ br, const float* __restrict__ A1)
{
    int n = blockIdx.x;
    int tid = threadIdx.x;
    __shared__ float xs[D_DIM];
    __shared__ float red[E_EXP][8];
    __shared__ float red2[16][8];
    __shared__ int s_idx[2];

    for (int d = tid; d < D_DIM; d += 256) xs[d] = x[(size_t)n * D_DIM + d];
    __syncthreads();

    // logits for all 8 experts
    float acc[E_EXP];
#pragma unroll
    for (int e = 0; e < E_EXP; e++) acc[e] = 0.f;
    for (int d = tid; d < D_DIM; d += 256) {
        float xv = xs[d];
#pragma unroll
        for (int e = 0; e < E_EXP; e++) acc[e] += xv * Wr[e * D_DIM + d];
    }
#pragma unroll
    for (int e = 0; e < E_EXP; e++) {
        float v = acc[e];
        for (int o = 16; o > 0; o >>= 1) v += __shfl_down_sync(0xffffffffu, v, o);
        if ((tid & 31) == 0) red[e][tid >> 5] = v;
    }
    __syncthreads();

    if (tid == 0) {
        float logits[E_EXP];
#pragma unroll
        for (int e = 0; e < E_EXP; e++) {
            float v = 0.f;
#pragma unroll
            for (int w = 0; w < 8; w++) v += red[e][w];
            logits[e] = v + br[e];
        }
        float mx = logits[0];
#pragma unroll
        for (int e = 1; e < E_EXP; e++) mx = fmaxf(mx, logits[e]);
        float p[E_EXP], se = 0.f;
#pragma unroll
        for (int e = 0; e < E_EXP; e++) { p[e] = expf(logits[e] - mx); se += p[e]; }
        float inv = 1.0f / se;
#pragma unroll
        for (int e = 0; e < E_EXP; e++) p[e] *= inv;
        // top-2, lowest index wins ties (matches jax top_k)
        int i0 = 0;
#pragma unroll
        for (int e = 1; e < E_EXP; e++) if (p[e] > p[i0]) i0 = e;
        int i1 = -1;
#pragma unroll
        for (int e = 0; e < E_EXP; e++) {
            if (e == i0) continue;
            if (i1 < 0 || p[e] > p[i1]) i1 = e;
        }
        s_idx[0] = i0; s_idx[1] = i1;
        eidx[2 * n] = i0; eidx[2 * n + 1] = i1;
        ew[2 * n] = p[i0]; ew[2 * n + 1] = p[i1];
        wsum_buf[n] = p[i0] + p[i1];
    }
    __syncthreads();

    // z1 coefficients for the 2 selected experts: 16 dots over D
    int e0 = s_idx[0], e1 = s_idx[1];
    float uacc[16];
#pragma unroll
    for (int i = 0; i < 16; i++) uacc[i] = 0.f;
    for (int d = tid; d < D_DIM; d += 256) {
        float xv = xs[d];
#pragma unroll
        for (int r = 0; r < R_RANK; r++) {
            uacc[r]     += xv * A1[((size_t)e0 * R_RANK + r) * D_DIM + d];
            uacc[8 + r] += xv * A1[((size_t)e1 * R_RANK + r) * D_DIM + d];
        }
    }
#pragma unroll
    for (int i = 0; i < 16; i++) {
        float v = uacc[i];
        for (int o = 16; o > 0; o >>= 1) v += __shfl_down_sync(0xffffffffu, v, o);
        if ((tid & 31) == 0) red2[i][tid >> 5] = v;
    }
    __syncthreads();
    if (tid < 16) {
        float v = 0.f;
#pragma unroll
        for (int w = 0; w < 8; w++) v += red2[tid][w];
        z1c[n * 16 + tid] = v * SCALING;
    }
}

// ---------------------------------------------------------------------------
// fc1: base = x @ W1^T, epilogue adds per-expert rank-8 LoRA, gelu,
// writes h0, h1 and g = w0*h0 + w1*h1.
// ---------------------------------------------------------------------------
__global__ __launch_bounds__(256, 2) void fc1_kernel(
    const float* __restrict__ A,   // x [N, D]
    const float* __restrict__ B,   // W1 [F, D]
    const float* __restrict__ b1,
    const float* __restrict__ B1)  // [E, F, R]
{
    const int K = D_DIM;
    int bn = blockIdx.x, bm = blockIdx.y;
    int tid = threadIdx.x;
    __shared__ float As[BK][BM + 4];
    __shared__ float Bs[BK][BN + 4];
    float acc[TM][TN];
#pragma unroll
    for (int i = 0; i < TM; i++)
#pragma unroll
        for (int j = 0; j < TN; j++) acc[i][j] = 0.f;

    int tx = tid % 16, ty = tid / 16;
    const float* Ab = A + (size_t)bm * BM * K;
    const float* Bb = B + (size_t)bn * BN * K;
    int rowL = tid >> 2;
    int colL = (tid & 3) * 4;

    for (int k0 = 0; k0 < K; k0 += BK) {
#pragma unroll
        for (int i = 0; i < 2; i++) {
            float4 a = *(const float4*)(Ab + (size_t)(rowL + i * 64) * K + k0 + colL);
            As[colL + 0][rowL + i * 64] = a.x;
            As[colL + 1][rowL + i * 64] = a.y;
            As[colL + 2][rowL + i * 64] = a.z;
            As[colL + 3][rowL + i * 64] = a.w;
            float4 b = *(const float4*)(Bb + (size_t)(rowL + i * 64) * K + k0 + colL);
            Bs[colL + 0][rowL + i * 64] = b.x;
            Bs[colL + 1][rowL + i * 64] = b.y;
            Bs[colL + 2][rowL + i * 64] = b.z;
            Bs[colL + 3][rowL + i * 64] = b.w;
        }
        __syncthreads();
#pragma unroll
        for (int kk = 0; kk < BK; kk++) {
            float4 a0 = *(const float4*)&As[kk][ty * TM];
            float4 a1 = *(const float4*)&As[kk][ty * TM + 4];
            float4 b0 = *(const float4*)&Bs[kk][tx * TN];
            float4 b1v = *(const float4*)&Bs[kk][tx * TN + 4];
            float ra[8] = {a0.x, a0.y, a0.z, a0.w, a1.x, a1.y, a1.z, a1.w};
            float rb[8] = {b0.x, b0.y, b0.z, b0.w, b1v.x, b1v.y, b1v.z, b1v.w};
#pragma unroll
            for (int i = 0; i < TM; i++)
#pragma unroll
                for (int j = 0; j < TN; j++) acc[i][j] += ra[i] * rb[j];
        }
        __syncthreads();
    }

    int nrow0 = bm * BM + ty * TM;
    int fcol0 = bn * BN + tx * TN;
#pragma unroll
    for (int i = 0; i < TM; i++) {
        int n = nrow0 + i;
        int e0 = eidx[2 * n], e1 = eidx[2 * n + 1];
        float w0 = ew[2 * n], w1 = ew[2 * n + 1];
        const float4* zp = (const float4*)&z1c[n * 16];
        float4 z0a = zp[0], z0b = zp[1], z1a = zp[2], z1b = zp[3];
        float h0v[TN], h1v[TN], gv[TN];
#pragma unroll
        for (int j = 0; j < TN; j++) {
            int f = fcol0 + j;
            float c = acc[i][j] + b1[f];
            const float4* q0 = (const float4*)&B1[((size_t)e0 * F_DIM + f) * R_RANK];
            float4 u0 = q0[0], u1 = q0[1];
            float l0 = z0a.x * u0.x + z0a.y * u0.y + z0a.z * u0.z + z0a.w * u0.w
                     + z0b.x * u1.x + z0b.y * u1.y + z0b.z * u1.z + z0b.w * u1.w;
            const float4* q1 = (const float4*)&B1[((size_t)e1 * F_DIM + f) * R_RANK];
            float4 v0 = q1[0], v1 = q1[1];
            float l1 = z1a.x * v0.x + z1a.y * v0.y + z1a.z * v0.z + z1a.w * v0.w
                     + z1b.x * v1.x + z1b.y * v1.y + z1b.z * v1.z + z1b.w * v1.w;
            float h0 = gelu_new(c + l0);
            float h1 = gelu_new(c + l1);
            h0v[j] = h0; h1v[j] = h1;
            gv[j] = w0 * h0 + w1 * h1;
        }
        size_t off = (size_t)n * F_DIM + fcol0;
        *(float4*)&h_buf[off]     = make_float4(h0v[0], h0v[1], h0v[2], h0v[3]);
        *(float4*)&h_buf[off + 4] = make_float4(h0v[4], h0v[5], h0v[6], h0v[7]);
        size_t off1 = off + (size_t)N_TOK * F_DIM;
        *(float4*)&h_buf[off1]     = make_float4(h1v[0], h1v[1], h1v[2], h1v[3]);
        *(float4*)&h_buf[off1 + 4] = make_float4(h1v[4], h1v[5], h1v[6], h1v[7]);
        *(float4*)&g_buf[off]     = make_float4(gv[0], gv[1], gv[2], gv[3]);
        *(float4*)&g_buf[off + 4] = make_float4(gv[4], gv[5], gv[6], gv[7]);
    }
}

// ---------------------------------------------------------------------------
// z2: z2s[n,k,r] = SCALING * w_k * sum_f h_k[n,f] * A2[e_k, r, f]
// One block per (token, k).
// ---------------------------------------------------------------------------
__global__ __launch_bounds__(256) void z2_kernel(const float* __restrict__ A2)
{
    int n = blockIdx.x;
    int k = blockIdx.y;
    int tid = threadIdx.x;
    int e = eidx[2 * n + k];
    const float* h = h_buf + (size_t)k * N_TOK * F_DIM + (size_t)n * F_DIM;
    const float* a2 = A2 + (size_t)e * R_RANK * F_DIM;

    float acc[R_RANK];
#pragma unroll
    for (int r = 0; r < R_RANK; r++) acc[r] = 0.f;

    for (int f = tid * 4; f < F_DIM; f += 1024) {
        float4 hv = *(const float4*)(h + f);
#pragma unroll
        for (int r = 0; r < R_RANK; r++) {
            float4 av = *(const float4*)(a2 + (size_t)r * F_DIM + f);
            acc[r] += hv.x * av.x + hv.y * av.y + hv.z * av.z + hv.w * av.w;
        }
    }

    __shared__ float red[R_RANK][8];
#pragma unroll
    for (int r = 0; r < R_RANK; r++) {
        float v = acc[r];
        for (int o = 16; o > 0; o >>= 1) v += __shfl_down_sync(0xffffffffu, v, o);
        if ((tid & 31) == 0) red[r][tid >> 5] = v;
    }
    __syncthreads();
    if (tid < R_RANK) {
        float v = 0.f;
#pragma unroll
        for (int w = 0; w < 8; w++) v += red[tid][w];
        z2s[n * 16 + k * 8 + tid] = v * SCALING * ew[2 * n + k];
    }
}

// ---------------------------------------------------------------------------
// fc2: out = g @ W2^T + (w0+w1)*b2 + sum_k z2s[n,k,:] . B2[e_k, d, :]
// ---------------------------------------------------------------------------
__global__ __launch_bounds__(256, 2) void fc2_kernel(
    const float* __restrict__ B,   // W2 [D, F]
    const float* __restrict__ b2,
    const float* __restrict__ B2,  // [E, D, R]
    float* __restrict__ out)
{
    const int K = F_DIM;
    int bn = blockIdx.x, bm = blockIdx.y;
    int tid = threadIdx.x;
    __shared__ float As[BK][BM + 4];
    __shared__ float Bs[BK][BN + 4];
    float acc[TM][TN];
#pragma unroll
    for (int i = 0; i < TM; i++)
#pragma unroll
        for (int j = 0; j < TN; j++) acc[i][j] = 0.f;

    int tx = tid % 16, ty = tid / 16;
    const float* Ab = g_buf + (size_t)bm * BM * K;
    const float* Bb = B + (size_t)bn * BN * K;
    int rowL = tid >> 2;
    int colL = (tid & 3) * 4;

    for (int k0 = 0; k0 < K; k0 += BK) {
#pragma unroll
        for (int i = 0; i < 2; i++) {
            float4 a = *(const float4*)(Ab + (size_t)(rowL + i * 64) * K + k0 + colL);
            As[colL + 0][rowL + i * 64] = a.x;
            As[colL + 1][rowL + i * 64] = a.y;
            As[colL + 2][rowL + i * 64] = a.z;
            As[colL + 3][rowL + i * 64] = a.w;
            float4 b = *(const float4*)(Bb + (size_t)(rowL + i * 64) * K + k0 + colL);
            Bs[colL + 0][rowL + i * 64] = b.x;
            Bs[colL + 1][rowL + i * 64] = b.y;
            Bs[colL + 2][rowL + i * 64] = b.z;
            Bs[colL + 3][rowL + i * 64] = b.w;
        }
        __syncthreads();
#pragma unroll
        for (int kk = 0; kk < BK; kk++) {
            float4 a0 = *(const float4*)&As[kk][ty * TM];
            float4 a1 = *(const float4*)&As[kk][ty * TM + 4];
            float4 b0 = *(const float4*)&Bs[kk][tx * TN];
            float4 b1v = *(const float4*)&Bs[kk][tx * TN + 4];
            float ra[8] = {a0.x, a0.y, a0.z, a0.w, a1.x, a1.y, a1.z, a1.w};
            float rb[8] = {b0.x, b0.y, b0.z, b0.w, b1v.x, b1v.y, b1v.z, b1v.w};
#pragma unroll
            for (int i = 0; i < TM; i++)
#pragma unroll
                for (int j = 0; j < TN; j++) acc[i][j] += ra[i] * rb[j];
        }
        __syncthreads();
    }

    int nrow0 = bm * BM + ty * TM;
    int dcol0 = bn * BN + tx * TN;
#pragma unroll
    for (int i = 0; i < TM; i++) {
        int n = nrow0 + i;
        float ws = wsum_buf[n];
        int e0 = eidx[2 * n], e1 = eidx[2 * n + 1];
        const float4* zp = (const float4*)&z2s[n * 16];
        float4 z0a = zp[0], z0b = zp[1], z1a = zp[2], z1b = zp[3];
        float ov[TN];
#pragma unroll
        for (int j = 0; j < TN; j++) {
            int d = dcol0 + j;
            float c = acc[i][j] + ws * b2[d];
            const float4* q0 = (const float4*)&B2[((size_t)e0 * D_DIM + d) * R_RANK];
            float4 u0 = q0[0], u1 = q0[1];
            c += z0a.x * u0.x + z0a.y * u0.y + z0a.z * u0.z + z0a.w * u0.w
               + z0b.x * u1.x + z0b.y * u1.y + z0b.z * u1.z + z0b.w * u1.w;
            const float4* q1 = (const float4*)&B2[((size_t)e1 * D_DIM + d) * R_RANK];
            float4 v0 = q1[0], v1 = q1[1];
            c += z1a.x * v0.x + z1a.y * v0.y + z1a.z * v0.z + z1a.w * v0.w
               + z1b.x * v1.x + z1b.y * v1.y + z1b.z * v1.z + z1b.w * v1.w;
            ov[j] = c;
        }
        size_t off = (size_t)n * D_DIM + dcol0;
        *(float4*)&out[off]     = make_float4(ov[0], ov[1], ov[2], ov[3]);
        *(float4*)&out[off + 4] = make_float4(ov[4], ov[5], ov[6], ov[7]);
    }
}

extern "C" void kernel_launch(void* const* d_in, const int* in_sizes, int n_in,
                              void* d_out, int out_size)
{
    const float* x  = (const float*)d_in[0];
    const float* Wr = (const float*)d_in[1];
    const float* br = (const float*)d_in[2];
    const float* W1 = (const float*)d_in[3];
    const float* b1 = (const float*)d_in[4];
    const float* W2 = (const float*)d_in[5];
    const float* b2 = (const float*)d_in[6];
    const float* A1 = (const float*)d_in[7];
    const float* B1 = (const float*)d_in[8];
    const float* A2 = (const float*)d_in[9];
    const float* B2 = (const float*)d_in[10];
    float* out = (float*)d_out;

    router_kernel<<<N_TOK, 256>>>(x, Wr, br, A1);
    fc1_kernel<<<dim3(F_DIM / BN, N_TOK / BM), 256>>>(x, W1, b1, B1);
    z2_kernel<<<dim3(N_TOK, 2), 256>>>(A2);
    fc2_kernel<<<dim3(D_DIM / BN, N_TOK / BM), 256>>>(W2, b2, B2, out);
}